// round 10
// baseline (speedup 1.0000x reference)
#include <cuda_runtime.h>
#include <cuda_fp16.h>
#include <cstdint>

// ---------------------------------------------------------------------------
// Problem constants
// ---------------------------------------------------------------------------
#define T_DIM 512
#define H_DIM 4096
#define I_DIM 11008

#define PITCH 80                 // bytes per 32-half smem row (ldmatrix-safe)
#define NK1 (H_DIM / 32)         // 128 k-stages, gemm1 tile (BK=32)
#define NK2 (I_DIM / 64)         // 172 k-stages, gemm2 tile (BK=64)

// Phase A (gemm1) smem: A(10240) + Bg(5120) + Bu(5120) = 20480/stage
#define G1_STAGE 20480

// Phase B (gemm2) smem: tile M=128, N=32, BK=64
#define G2_PITCH 144                        // 64-half rows: 128B + 16 pad
#define G2_A_BYTES (128 * G2_PITCH)         // 18432
#define G2_B_BYTES (64 * PITCH)             // 5120 : B [64 k][32 h]
#define G2_STAGE (G2_A_BYTES + G2_B_BYTES)  // 23552
#define FUSED_SMEM (2 * G2_STAGE)           // 47104 >= 2*G1_STAGE

#define N_A_TILES 688            // 4 t-tiles x 172 i-tiles (t0-major)
#define N_B_TILES 512            // 4 t-tiles x 128 h-tiles (t0-major)
#define GRID_FUSED 296           // 148 SMs x occ 2

// Scratch + schedule state (device globals — allocations are forbidden)
__device__ __align__(256) __half g_h[(size_t)T_DIM * I_DIM];   // 11.3 MB
__device__ __align__(256) __half g_x[(size_t)T_DIM * H_DIM];   // 4 MB
__device__ int g_tickets[2];     // [0]=A ticket, [1]=B ticket
__device__ int g_done[4];        // per-t0 completed gemm1 i-tiles

// ---------------------------------------------------------------------------
// sm_80-baseline PTX helpers (NO tcgen05 — harness targets compute_103 non-'a')
// ---------------------------------------------------------------------------
__device__ __forceinline__ uint32_t smem_u32(const void* p) {
    uint32_t a;
    asm("{ .reg .u64 t; cvta.to.shared.u64 t, %1; cvt.u32.u64 %0, t; }"
        : "=r"(a) : "l"(p));
    return a;
}

__device__ __forceinline__ void ldsm_x4(uint32_t* r, uint32_t addr) {
    asm volatile("ldmatrix.sync.aligned.m8n8.x4.shared.b16 {%0,%1,%2,%3}, [%4];"
                 : "=r"(r[0]), "=r"(r[1]), "=r"(r[2]), "=r"(r[3]) : "r"(addr));
}

__device__ __forceinline__ void ldsm_x4_t(uint32_t* r, uint32_t addr) {
    asm volatile("ldmatrix.sync.aligned.m8n8.x4.trans.shared.b16 {%0,%1,%2,%3}, [%4];"
                 : "=r"(r[0]), "=r"(r[1]), "=r"(r[2]), "=r"(r[3]) : "r"(addr));
}

__device__ __forceinline__ void mma16816(float* c, const uint32_t* a, const uint32_t* b) {
    asm volatile(
        "mma.sync.aligned.m16n8k16.row.col.f32.f16.f16.f32 "
        "{%0,%1,%2,%3}, {%4,%5,%6,%7}, {%8,%9}, {%0,%1,%2,%3};"
        : "+f"(c[0]), "+f"(c[1]), "+f"(c[2]), "+f"(c[3])
        : "r"(a[0]), "r"(a[1]), "r"(a[2]), "r"(a[3]), "r"(b[0]), "r"(b[1]));
}

__device__ __forceinline__ void cp16(uint32_t sdst, const void* gsrc) {
    asm volatile("cp.async.cg.shared.global [%0], [%1], 16;"
                 :: "r"(sdst), "l"(__cvta_generic_to_global(gsrc)));
}
#define CP_COMMIT() asm volatile("cp.async.commit_group;")
#define CP_WAIT0()  asm volatile("cp.async.wait_group 0;")

// ---------------------------------------------------------------------------
// Kernel 0: x fp32 -> g_x fp16; also resets schedule counters for this launch
// ---------------------------------------------------------------------------
__global__ __launch_bounds__(256) void cvt_x_kernel(const float* __restrict__ x) {
    if (blockIdx.x == 0 && threadIdx.x < 6) {
        if (threadIdx.x < 2) g_tickets[threadIdx.x] = 0;
        else                 g_done[threadIdx.x - 2] = 0;
    }
    size_t i = (size_t)blockIdx.x * 256 + threadIdx.x;   // float4 index
    float4 v = reinterpret_cast<const float4*>(x)[i];
    __half2 h0 = __floats2half2_rn(v.x, v.y);
    __half2 h1 = __floats2half2_rn(v.z, v.w);
    uint2 w;
    w.x = *(uint32_t*)&h0; w.y = *(uint32_t*)&h1;
    reinterpret_cast<uint2*>(g_x)[i] = w;
}

// ---------------------------------------------------------------------------
// Phase A staging (gemm1: tile 128x64 per matrix, BK=32)
// ---------------------------------------------------------------------------
__device__ __forceinline__ void cp_a_g1(uint32_t sA, int t0, int k0, int tid) {
#pragma unroll
    for (int j = 0; j < 2; j++) {            // 128 rows x 4 chunks (16B)
        int idx = tid + j * 256;
        int r = idx >> 2, c = idx & 3;
        cp16(sA + r * PITCH + c * 16, g_x + (size_t)(t0 + r) * H_DIM + k0 + c * 8);
    }
    CP_COMMIT();
}

__device__ __forceinline__ void ldg_b_g1(const float* __restrict__ wg,
                                         const float* __restrict__ wu,
                                         int i0, int k0, int tid,
                                         float4* bgv, float4* buv) {
#pragma unroll
    for (int j = 0; j < 2; j++) {            // 64 rows x 8 float4
        int idx = tid + j * 256;
        int r = idx >> 3, c = idx & 7;
        bgv[j] = *(const float4*)(wg + (size_t)(i0 + r) * H_DIM + k0 + c * 4);
        buv[j] = *(const float4*)(wu + (size_t)(i0 + r) * H_DIM + k0 + c * 4);
    }
}

__device__ __forceinline__ void sts_b_g1(char* st, int tid, float sgv, float suv,
                                         const float4* bgv, const float4* buv) {
#pragma unroll
    for (int j = 0; j < 2; j++) {
        int idx = tid + j * 256;
        int r = idx >> 3, c = idx & 7;
        {
            __half2 h0 = __floats2half2_rn(bgv[j].x * sgv, bgv[j].y * sgv);
            __half2 h1 = __floats2half2_rn(bgv[j].z * sgv, bgv[j].w * sgv);
            uint2 w;
            w.x = *(uint32_t*)&h0; w.y = *(uint32_t*)&h1;
            *(uint2*)(st + 10240 + r * PITCH + c * 8) = w;
        }
        {
            __half2 h0 = __floats2half2_rn(buv[j].x * suv, buv[j].y * suv);
            __half2 h1 = __floats2half2_rn(buv[j].z * suv, buv[j].w * suv);
            uint2 w;
            w.x = *(uint32_t*)&h0; w.y = *(uint32_t*)&h1;
            *(uint2*)(st + 15360 + r * PITCH + c * 8) = w;
        }
    }
}

// Phase A tile body: gate/up dual GEMM + SwiGLU -> g_h
__device__ __forceinline__ void run_a_tile(
    char* sm, uint32_t sbase, int t0, int i0, int tid, int wid, int l,
    const float* __restrict__ wg, const float* __restrict__ wu,
    const float* __restrict__ sg, const float* __restrict__ su) {
    const int wm = wid & 3, wn = wid >> 2;
    const int iblk = i0 >> 7;

    float cg[2][4][4], cu[2][4][4];
#pragma unroll
    for (int a = 0; a < 2; a++)
#pragma unroll
        for (int b = 0; b < 4; b++)
#pragma unroll
            for (int d = 0; d < 4; d++) { cg[a][b][d] = 0.f; cu[a][b][d] = 0.f; }

    float4 bgv[2], buv[2];
    cp_a_g1(sbase, t0, 0, tid);
    ldg_b_g1(wg, wu, i0, 0, tid, bgv, buv);
    sts_b_g1(sm, tid, __ldg(sg + iblk * 32), __ldg(su + iblk * 32), bgv, buv);
    CP_WAIT0();
    __syncthreads();

    for (int it = 0; it < NK1; it++) {
        float sgv = 0.f, suv = 0.f;
        if (it + 1 < NK1) {
            cp_a_g1(sbase + ((it + 1) & 1) * G1_STAGE, t0, (it + 1) * 32, tid);
            ldg_b_g1(wg, wu, i0, (it + 1) * 32, tid, bgv, buv);
            int kb = (it + 1) >> 2;
            sgv = __ldg(sg + iblk * 32 + kb);
            suv = __ldg(su + iblk * 32 + kb);
        }

        const uint32_t sA = sbase + (it & 1) * G1_STAGE;
        const uint32_t sBg = sA + 10240;
        const uint32_t sBu = sA + 15360;
#pragma unroll
        for (int kk = 0; kk < 32; kk += 16) {
            uint32_t a2[2][4];
#pragma unroll
            for (int mi = 0; mi < 2; mi++)
                ldsm_x4(a2[mi], sA + (wm * 32 + mi * 16 + (l & 15)) * PITCH +
                                   (kk + ((l >> 4) << 3)) * 2);
            uint32_t bg[4][2], bu[4][2];
#pragma unroll
            for (int p = 0; p < 2; p++) {
                int m = l >> 3;
                int row = wn * 32 + (p * 2 + (m >> 1)) * 8 + (l & 7);
                uint32_t aoff = row * PITCH + (kk + (m & 1) * 8) * 2;
                uint32_t r4[4];
                ldsm_x4(r4, sBg + aoff);
                bg[p * 2][0] = r4[0]; bg[p * 2][1] = r4[1];
                bg[p * 2 + 1][0] = r4[2]; bg[p * 2 + 1][1] = r4[3];
                ldsm_x4(r4, sBu + aoff);
                bu[p * 2][0] = r4[0]; bu[p * 2][1] = r4[1];
                bu[p * 2 + 1][0] = r4[2]; bu[p * 2 + 1][1] = r4[3];
            }
#pragma unroll
            for (int mi = 0; mi < 2; mi++)
#pragma unroll
                for (int n = 0; n < 4; n++) {
                    mma16816(cg[mi][n], a2[mi], bg[n]);
                    mma16816(cu[mi][n], a2[mi], bu[n]);
                }
        }

        if (it + 1 < NK1) {
            sts_b_g1(sm + ((it + 1) & 1) * G1_STAGE, tid, sgv, suv, bgv, buv);
            CP_WAIT0();
        }
        __syncthreads();
    }

    // Epilogue: h = silu(gate) * up -> fp16 g_h
#pragma unroll
    for (int mi = 0; mi < 2; mi++)
#pragma unroll
        for (int n = 0; n < 4; n++) {
            int row = t0 + wm * 32 + mi * 16 + (l >> 2);
            int col = i0 + wn * 32 + n * 8 + ((l & 3) << 1);
            {
                float g0 = cg[mi][n][0], g1 = cg[mi][n][1];
                float h0 = g0 * cu[mi][n][0] / (1.0f + __expf(-g0));
                float h1 = g1 * cu[mi][n][1] / (1.0f + __expf(-g1));
                __half2 hv = __floats2half2_rn(h0, h1);
                *(uint32_t*)(&g_h[(size_t)row * I_DIM + col]) = *(uint32_t*)&hv;
            }
            {
                float g0 = cg[mi][n][2], g1 = cg[mi][n][3];
                float h0 = g0 * cu[mi][n][2] / (1.0f + __expf(-g0));
                float h1 = g1 * cu[mi][n][3] / (1.0f + __expf(-g1));
                __half2 hv = __floats2half2_rn(h0, h1);
                *(uint32_t*)(&g_h[(size_t)(row + 8) * I_DIM + col]) = *(uint32_t*)&hv;
            }
        }
}

// ---------------------------------------------------------------------------
// Phase B staging (gemm2: tile 128x32, BK=64)
// ---------------------------------------------------------------------------
__device__ __forceinline__ void cp_a_g2(uint32_t sA, int t0, int k0, int tid) {
#pragma unroll
    for (int j = 0; j < 4; j++) {            // 128 rows x 8 chunks (16B)
        int idx = tid + j * 256;
        int r = idx >> 3, c = idx & 7;
        cp16(sA + r * G2_PITCH + c * 16, g_h + (size_t)(t0 + r) * I_DIM + k0 + c * 8);
    }
    CP_COMMIT();
}

__device__ __forceinline__ void ldg_b_g2(const float* __restrict__ wd,
                                         int h0, int k0, int tid, float4* b4) {
#pragma unroll
    for (int j = 0; j < 2; j++) {            // 64 k-rows x 8 float4
        int idx = tid + j * 256;
        int r = idx >> 3, c4 = idx & 7;
        b4[j] = *(const float4*)(wd + (size_t)(k0 + r) * H_DIM + h0 + c4 * 4);
    }
}

__device__ __forceinline__ void sts_b_g2(char* st, int tid, float s, const float4* b4) {
#pragma unroll
    for (int j = 0; j < 2; j++) {
        int idx = tid + j * 256;
        int r = idx >> 3, c4 = idx & 7;
        __half2 h0 = __floats2half2_rn(b4[j].x * s, b4[j].y * s);
        __half2 h1 = __floats2half2_rn(b4[j].z * s, b4[j].w * s);
        uint2 w;
        w.x = *(uint32_t*)&h0; w.y = *(uint32_t*)&h1;
        *(uint2*)(st + G2_A_BYTES + r * PITCH + c4 * 8) = w;
    }
}

// Phase B tile body: out = g_h x dequant(Wd)
__device__ __forceinline__ void run_b_tile(
    char* sm, uint32_t sbase, int t0, int h0, int tid, int wid, int l,
    const float* __restrict__ wd, const float* __restrict__ sd,
    float* __restrict__ out) {
    const int wm = wid & 3, wn = wid >> 2;   // wn in 0..1 -> 16-col halves
    const int hb = h0 >> 7;

    float c[2][2][4];
#pragma unroll
    for (int a = 0; a < 2; a++)
#pragma unroll
        for (int b = 0; b < 2; b++)
#pragma unroll
            for (int d = 0; d < 4; d++) c[a][b][d] = 0.f;

    float4 b4[2];
    cp_a_g2(sbase, t0, 0, tid);
    ldg_b_g2(wd, h0, 0, tid, b4);
    sts_b_g2(sm, tid, __ldg(sd + hb), b4);
    CP_WAIT0();
    __syncthreads();

    for (int it = 0; it < NK2; it++) {
        float sv = 0.f;
        if (it + 1 < NK2) {
            cp_a_g2(sbase + ((it + 1) & 1) * G2_STAGE, t0, (it + 1) * 64, tid);
            ldg_b_g2(wd, h0, (it + 1) * 64, tid, b4);
            sv = __ldg(sd + ((it + 1) >> 1) * (H_DIM / 128) + hb);
        }

        const uint32_t sA = sbase + (it & 1) * G2_STAGE;
        const uint32_t sB = sA + G2_A_BYTES;
#pragma unroll
        for (int kk = 0; kk < 64; kk += 16) {
            uint32_t a2[2][4];
#pragma unroll
            for (int mi = 0; mi < 2; mi++)
                ldsm_x4(a2[mi], sA + (wm * 32 + mi * 16 + (l & 15)) * G2_PITCH +
                                   (kk + ((l >> 4) << 3)) * 2);
            uint32_t bf[2][2];
            {
                // ldmatrix.trans of [k][h] tile: (t&1)=k-half, (t>>1)=n-half
                int t = l >> 3, rr = l & 7;
                uint32_t baddr = sB + (kk + (t & 1) * 8 + rr) * PITCH +
                                 (wn * 16 + (t >> 1) * 8) * 2;
                uint32_t r4[4];
                ldsm_x4_t(r4, baddr);
                bf[0][0] = r4[0]; bf[0][1] = r4[1];
                bf[1][0] = r4[2]; bf[1][1] = r4[3];
            }
#pragma unroll
            for (int mi = 0; mi < 2; mi++)
#pragma unroll
                for (int n = 0; n < 2; n++)
                    mma16816(c[mi][n], a2[mi], bf[n]);
        }

        if (it + 1 < NK2) {
            sts_b_g2(sm + ((it + 1) & 1) * G2_STAGE, tid, sv, b4);
            CP_WAIT0();
        }
        __syncthreads();
    }

    // Epilogue: fp32 stores
#pragma unroll
    for (int mi = 0; mi < 2; mi++)
#pragma unroll
        for (int n = 0; n < 2; n++) {
            int row = t0 + wm * 32 + mi * 16 + (l >> 2);
            int col = h0 + wn * 16 + n * 8 + ((l & 3) << 1);
            float2 v0 = make_float2(c[mi][n][0], c[mi][n][1]);
            float2 v1 = make_float2(c[mi][n][2], c[mi][n][3]);
            *(float2*)(out + (size_t)row * H_DIM + col) = v0;
            *(float2*)(out + (size_t)(row + 8) * H_DIM + col) = v1;
        }
}

// ---------------------------------------------------------------------------
// Fused persistent kernel: ticket-scheduled gemm1 tiles, then gemm2 tiles
// gated on per-t0 completion counters (overlaps gemm1 tail with gemm2 head).
// ---------------------------------------------------------------------------
__global__ __launch_bounds__(256, 2) void fused_mlp_kernel(
    const float* __restrict__ wg, const float* __restrict__ wu,
    const float* __restrict__ sg, const float* __restrict__ su,
    const float* __restrict__ wd, const float* __restrict__ sd,
    float* __restrict__ out) {
    extern __shared__ __align__(128) char sm[];
    __shared__ int s_ticket;
    const int tid = threadIdx.x, wid = tid >> 5, l = tid & 31;
    const uint32_t sbase = smem_u32(sm);

    // ---- Phase A: gemm1 tiles (t0-major so t0 completes in order) ----
    for (;;) {
        if (tid == 0) s_ticket = atomicAdd(&g_tickets[0], 1);
        __syncthreads();
        int a = s_ticket;
        __syncthreads();
        if (a >= N_A_TILES) break;
        int t0 = (a / 172) * 128;
        int i0 = (a % 172) * 64;
        run_a_tile(sm, sbase, t0, i0, tid, wid, l, wg, wu, sg, su);
        __threadfence();
        __syncthreads();
        if (tid == 0) atomicAdd(&g_done[a / 172], 1);
    }

    // ---- Phase B: gemm2 tiles, each gated on its t0's 172 gemm1 tiles ----
    for (;;) {
        if (tid == 0) s_ticket = atomicAdd(&g_tickets[1], 1);
        __syncthreads();
        int b = s_ticket;
        __syncthreads();
        if (b >= N_B_TILES) break;
        int tb = b / 128;
        int h0 = (b % 128) * 32;
        if (tid == 0) {
            while (atomicAdd(&g_done[tb], 0) < 172) __nanosleep(64);
        }
        __syncthreads();
        __threadfence();
        run_b_tile(sm, sbase, tb * 128, h0, tid, wid, l, wd, sd, out);
    }
}

// ---------------------------------------------------------------------------
// Launch
// ---------------------------------------------------------------------------
extern "C" void kernel_launch(void* const* d_in, const int* in_sizes, int n_in,
                              void* d_out, int out_size) {
    const float* x  = (const float*)d_in[0];
    const float* wg = (const float*)d_in[1];
    const float* wu = (const float*)d_in[2];
    const float* wd = (const float*)d_in[3];
    const float* sg = (const float*)d_in[4];
    const float* su = (const float*)d_in[5];
    const float* sd = (const float*)d_in[6];
    float* out = (float*)d_out;
    (void)in_sizes; (void)n_in; (void)out_size;

    cudaFuncSetAttribute(fused_mlp_kernel, cudaFuncAttributeMaxDynamicSharedMemorySize,
                         FUSED_SMEM);

    cvt_x_kernel<<<(T_DIM * H_DIM / 4) / 256, 256>>>(x);
    fused_mlp_kernel<<<GRID_FUSED, 256, FUSED_SMEM>>>(wg, wu, sg, su, wd, sd, out);
}

// round 11
// speedup vs baseline: 1.4492x; 1.4492x over previous
#include <cuda_runtime.h>
#include <cuda_fp16.h>
#include <cstdint>

// ---------------------------------------------------------------------------
// Problem constants
// ---------------------------------------------------------------------------
#define T_DIM 512
#define H_DIM 4096
#define I_DIM 11008

#define PITCH 80                 // bytes per 32-half smem row (ldmatrix-safe)
#define NK1 (H_DIM / 64)         // 64 k-stages for gemm1 (BK=64)
#define NK2 (I_DIM / 64)         // 172 k-stages for gemm2 (BK=64)

// gemm1: tile M=128, N=64 (per matrix), BK=64. pitch 144 = 9x16B
#define G1_PITCH 144
#define G1_A_BYTES (128 * G1_PITCH)          // 18432 : A [128 t][64 k halfs]
#define G1_B_BYTES (64 * G1_PITCH)           // 9216  : Bg/Bu [64 i][64 k halfs]
#define G1_STAGE (G1_A_BYTES + 2 * G1_B_BYTES)   // 36864
#define G1_SMEM (2 * G1_STAGE)                   // 73728 (dynamic)

// gemm2: tile M=128, N=64, BK=64. pitch 144
#define G2_PITCH 144
#define G2_A_BYTES (128 * G2_PITCH)     // 18432 : A [128 t][64 k halfs]
#define G2_B_BYTES (64 * G2_PITCH)      // 9216  : B [64 k][64 h halfs]
#define G2_STAGE (G2_A_BYTES + G2_B_BYTES)  // 27648
#define G2_SMEM (2 * G2_STAGE)              // 55296 (dynamic)

// Scratch (device globals — allocations are forbidden)
__device__ __align__(256) __half g_h[(size_t)T_DIM * I_DIM];   // 11.3 MB
__device__ __align__(256) __half g_x[(size_t)T_DIM * H_DIM];   // 4 MB

// ---------------------------------------------------------------------------
// sm_80-baseline PTX helpers (NO tcgen05 — harness targets compute_103 non-'a')
// ---------------------------------------------------------------------------
__device__ __forceinline__ uint32_t smem_u32(const void* p) {
    uint32_t a;
    asm("{ .reg .u64 t; cvta.to.shared.u64 t, %1; cvt.u32.u64 %0, t; }"
        : "=r"(a) : "l"(p));
    return a;
}

__device__ __forceinline__ void ldsm_x4(uint32_t* r, uint32_t addr) {
    asm volatile("ldmatrix.sync.aligned.m8n8.x4.shared.b16 {%0,%1,%2,%3}, [%4];"
                 : "=r"(r[0]), "=r"(r[1]), "=r"(r[2]), "=r"(r[3]) : "r"(addr));
}

__device__ __forceinline__ void ldsm_x4_t(uint32_t* r, uint32_t addr) {
    asm volatile("ldmatrix.sync.aligned.m8n8.x4.trans.shared.b16 {%0,%1,%2,%3}, [%4];"
                 : "=r"(r[0]), "=r"(r[1]), "=r"(r[2]), "=r"(r[3]) : "r"(addr));
}

__device__ __forceinline__ void mma16816(float* c, const uint32_t* a, const uint32_t* b) {
    asm volatile(
        "mma.sync.aligned.m16n8k16.row.col.f32.f16.f16.f32 "
        "{%0,%1,%2,%3}, {%4,%5,%6,%7}, {%8,%9}, {%0,%1,%2,%3};"
        : "+f"(c[0]), "+f"(c[1]), "+f"(c[2]), "+f"(c[3])
        : "r"(a[0]), "r"(a[1]), "r"(a[2]), "r"(a[3]), "r"(b[0]), "r"(b[1]));
}

__device__ __forceinline__ void cp16(uint32_t sdst, const void* gsrc) {
    asm volatile("cp.async.cg.shared.global [%0], [%1], 16;"
                 :: "r"(sdst), "l"(__cvta_generic_to_global(gsrc)));
}
#define CP_COMMIT() asm volatile("cp.async.commit_group;")
#define CP_WAIT0()  asm volatile("cp.async.wait_group 0;")

// ---------------------------------------------------------------------------
// Kernel 0: x fp32 -> g_x fp16 (tiny streaming convert)
// ---------------------------------------------------------------------------
__global__ __launch_bounds__(256) void cvt_x_kernel(const float* __restrict__ x) {
    size_t i = (size_t)blockIdx.x * 256 + threadIdx.x;   // float4 index
    float4 v = reinterpret_cast<const float4*>(x)[i];
    __half2 h0 = __floats2half2_rn(v.x, v.y);
    __half2 h1 = __floats2half2_rn(v.z, v.w);
    uint2 w;
    w.x = *(uint32_t*)&h0; w.y = *(uint32_t*)&h1;
    reinterpret_cast<uint2*>(g_x)[i] = w;
}

// ---------------------------------------------------------------------------
// GEMM1 staging (BK=64)
// ---------------------------------------------------------------------------
__device__ __forceinline__ void cp_a_g1(uint32_t sA, int t0, int k0, int tid) {
#pragma unroll
    for (int j = 0; j < 4; j++) {            // 128 rows x 8 chunks (16B)
        int idx = tid + j * 256;
        int r = idx >> 3, c = idx & 7;
        cp16(sA + r * G1_PITCH + c * 16, g_x + (size_t)(t0 + r) * H_DIM + k0 + c * 8);
    }
    CP_COMMIT();
}

__device__ __forceinline__ void ldg_b_g1(const float* __restrict__ wg,
                                         const float* __restrict__ wu,
                                         int i0, int k0, int tid,
                                         float4* bgv, float4* buv) {
#pragma unroll
    for (int j = 0; j < 4; j++) {            // 64 rows x 16 float4
        int idx = tid + j * 256;
        int r = idx >> 4, c = idx & 15;
        bgv[j] = *(const float4*)(wg + (size_t)(i0 + r) * H_DIM + k0 + c * 4);
        buv[j] = *(const float4*)(wu + (size_t)(i0 + r) * H_DIM + k0 + c * 4);
    }
}

__device__ __forceinline__ void sts_b_g1(char* st, int tid, float sgv, float suv,
                                         const float4* bgv, const float4* buv) {
#pragma unroll
    for (int j = 0; j < 4; j++) {
        int idx = tid + j * 256;
        int r = idx >> 4, c = idx & 15;
        {
            __half2 h0 = __floats2half2_rn(bgv[j].x * sgv, bgv[j].y * sgv);
            __half2 h1 = __floats2half2_rn(bgv[j].z * sgv, bgv[j].w * sgv);
            uint2 w;
            w.x = *(uint32_t*)&h0; w.y = *(uint32_t*)&h1;
            *(uint2*)(st + G1_A_BYTES + r * G1_PITCH + c * 8) = w;
        }
        {
            __half2 h0 = __floats2half2_rn(buv[j].x * suv, buv[j].y * suv);
            __half2 h1 = __floats2half2_rn(buv[j].z * suv, buv[j].w * suv);
            uint2 w;
            w.x = *(uint32_t*)&h0; w.y = *(uint32_t*)&h1;
            *(uint2*)(st + G1_A_BYTES + G1_B_BYTES + r * G1_PITCH + c * 8) = w;
        }
    }
}

// ---------------------------------------------------------------------------
// Kernel 1: gate/up dual GEMM + SwiGLU -> g_h (fp16)
//   CTA: M=128 (T), N=64 (I) per matrix, BK=64. 8 warps = 4(M) x 2(N).
//   A via cp.async from g_x; B via reg-buffered LDG + fused dequant-cvt.
// ---------------------------------------------------------------------------
__global__ __launch_bounds__(256, 2) void gemm1_kernel(
    const float* __restrict__ wg, const float* __restrict__ wu,
    const float* __restrict__ sg, const float* __restrict__ su) {
    extern __shared__ __align__(128) char sm[];
    const int tid = threadIdx.x, wid = tid >> 5, l = tid & 31;
    const int wm = wid & 3, wn = wid >> 2;
    const int t0 = blockIdx.x * 128, i0 = blockIdx.y * 64;
    const int iblk = i0 >> 7;
    const uint32_t sbase = smem_u32(sm);

    float cg[2][4][4], cu[2][4][4];
#pragma unroll
    for (int a = 0; a < 2; a++)
#pragma unroll
        for (int b = 0; b < 4; b++)
#pragma unroll
            for (int d = 0; d < 4; d++) { cg[a][b][d] = 0.f; cu[a][b][d] = 0.f; }

    float4 bgv[4], buv[4];
    cp_a_g1(sbase, t0, 0, tid);
    ldg_b_g1(wg, wu, i0, 0, tid, bgv, buv);
    sts_b_g1(sm, tid, __ldg(sg + iblk * 32), __ldg(su + iblk * 32), bgv, buv);
    CP_WAIT0();
    __syncthreads();

    for (int it = 0; it < NK1; it++) {
        float sgv = 0.f, suv = 0.f;
        if (it + 1 < NK1) {
            cp_a_g1(sbase + ((it + 1) & 1) * G1_STAGE, t0, (it + 1) * 64, tid);
            ldg_b_g1(wg, wu, i0, (it + 1) * 64, tid, bgv, buv);
            int kb = (it + 1) >> 1;              // 128-wide k-blocks
            sgv = __ldg(sg + iblk * 32 + kb);
            suv = __ldg(su + iblk * 32 + kb);
        }

        const uint32_t sA = sbase + (it & 1) * G1_STAGE;
        const uint32_t sBg = sA + G1_A_BYTES;
        const uint32_t sBu = sBg + G1_B_BYTES;
#pragma unroll
        for (int kk = 0; kk < 64; kk += 16) {
            uint32_t a2[2][4];
#pragma unroll
            for (int mi = 0; mi < 2; mi++)
                ldsm_x4(a2[mi], sA + (wm * 32 + mi * 16 + (l & 15)) * G1_PITCH +
                                   (kk + ((l >> 4) << 3)) * 2);
            uint32_t bg[4][2], bu[4][2];
#pragma unroll
            for (int p = 0; p < 2; p++) {
                int m = l >> 3;
                int row = wn * 32 + (p * 2 + (m >> 1)) * 8 + (l & 7);
                uint32_t aoff = row * G1_PITCH + (kk + (m & 1) * 8) * 2;
                uint32_t r4[4];
                ldsm_x4(r4, sBg + aoff);
                bg[p * 2][0] = r4[0]; bg[p * 2][1] = r4[1];
                bg[p * 2 + 1][0] = r4[2]; bg[p * 2 + 1][1] = r4[3];
                ldsm_x4(r4, sBu + aoff);
                bu[p * 2][0] = r4[0]; bu[p * 2][1] = r4[1];
                bu[p * 2 + 1][0] = r4[2]; bu[p * 2 + 1][1] = r4[3];
            }
#pragma unroll
            for (int mi = 0; mi < 2; mi++)
#pragma unroll
                for (int n = 0; n < 4; n++) {
                    mma16816(cg[mi][n], a2[mi], bg[n]);
                    mma16816(cu[mi][n], a2[mi], bu[n]);
                }
        }

        if (it + 1 < NK1) {
            sts_b_g1(sm + ((it + 1) & 1) * G1_STAGE, tid, sgv, suv, bgv, buv);
            CP_WAIT0();
        }
        __syncthreads();
    }

    // Epilogue: h = silu(gate) * up -> fp16 g_h
#pragma unroll
    for (int mi = 0; mi < 2; mi++)
#pragma unroll
        for (int n = 0; n < 4; n++) {
            int row = t0 + wm * 32 + mi * 16 + (l >> 2);
            int col = i0 + wn * 32 + n * 8 + ((l & 3) << 1);
            {
                float g0 = cg[mi][n][0], g1 = cg[mi][n][1];
                float h0 = g0 * cu[mi][n][0] / (1.0f + __expf(-g0));
                float h1 = g1 * cu[mi][n][1] / (1.0f + __expf(-g1));
                __half2 hv = __floats2half2_rn(h0, h1);
                *(uint32_t*)(&g_h[(size_t)row * I_DIM + col]) = *(uint32_t*)&hv;
            }
            {
                float g0 = cg[mi][n][2], g1 = cg[mi][n][3];
                float h0 = g0 * cu[mi][n][2] / (1.0f + __expf(-g0));
                float h1 = g1 * cu[mi][n][3] / (1.0f + __expf(-g1));
                __half2 hv = __floats2half2_rn(h0, h1);
                *(uint32_t*)(&g_h[(size_t)(row + 8) * I_DIM + col]) = *(uint32_t*)&hv;
            }
        }
}

// ---------------------------------------------------------------------------
// GEMM2 staging (tile 128x64, BK=64)
// ---------------------------------------------------------------------------
__device__ __forceinline__ void cp_a_g2(uint32_t sA, int t0, int k0, int tid) {
#pragma unroll
    for (int j = 0; j < 4; j++) {            // 128 rows x 8 chunks (16B)
        int idx = tid + j * 256;
        int r = idx >> 3, c = idx & 7;
        cp16(sA + r * G2_PITCH + c * 16, g_h + (size_t)(t0 + r) * I_DIM + k0 + c * 8);
    }
    CP_COMMIT();
}

__device__ __forceinline__ void ldg_b_g2(const float* __restrict__ wd,
                                         int h0, int k0, int tid, float4* b4) {
#pragma unroll
    for (int j = 0; j < 4; j++) {            // 64 k-rows x 16 float4
        int idx = tid + j * 256;
        int r = idx >> 4, c4 = idx & 15;
        b4[j] = *(const float4*)(wd + (size_t)(k0 + r) * H_DIM + h0 + c4 * 4);
    }
}

__device__ __forceinline__ void sts_b_g2(char* st, int tid, float s, const float4* b4) {
#pragma unroll
    for (int j = 0; j < 4; j++) {
        int idx = tid + j * 256;
        int r = idx >> 4, c4 = idx & 15;
        __half2 h0 = __floats2half2_rn(b4[j].x * s, b4[j].y * s);
        __half2 h1 = __floats2half2_rn(b4[j].z * s, b4[j].w * s);
        uint2 w;
        w.x = *(uint32_t*)&h0; w.y = *(uint32_t*)&h1;
        *(uint2*)(st + G2_A_BYTES + r * G2_PITCH + c4 * 8) = w;
    }
}

// ---------------------------------------------------------------------------
// Kernel 2: out[T,H] = g_h[T,I] x dequant(Wd)[I,H]  (fp16 mma, fp32 out)
//   CTA: 128x64, BK=64. 8 warps = 4(M) x 2(N). Warp tile 32x32.
//   B frags via ldmatrix.x4.trans from [k][h] tile.
// ---------------------------------------------------------------------------
__global__ __launch_bounds__(256, 2) void gemm2_kernel(
    const float* __restrict__ wd, const float* __restrict__ sd,
    float* __restrict__ out) {
    extern __shared__ __align__(128) char sm2[];
    const int tid = threadIdx.x, wid = tid >> 5, l = tid & 31;
    const int wm = wid & 3, wn = wid >> 2;
    const int t0 = blockIdx.x * 128, h0 = blockIdx.y * 64;
    const int hb = h0 >> 7;
    const uint32_t sbase = smem_u32(sm2);

    float c[2][4][4];
#pragma unroll
    for (int a = 0; a < 2; a++)
#pragma unroll
        for (int b = 0; b < 4; b++)
#pragma unroll
            for (int d = 0; d < 4; d++) c[a][b][d] = 0.f;

    float4 b4[4];
    cp_a_g2(sbase, t0, 0, tid);
    ldg_b_g2(wd, h0, 0, tid, b4);
    sts_b_g2(sm2, tid, __ldg(sd + hb), b4);
    CP_WAIT0();
    __syncthreads();

    for (int it = 0; it < NK2; it++) {
        float sv = 0.f;
        if (it + 1 < NK2) {
            cp_a_g2(sbase + ((it + 1) & 1) * G2_STAGE, t0, (it + 1) * 64, tid);
            ldg_b_g2(wd, h0, (it + 1) * 64, tid, b4);
            sv = __ldg(sd + ((it + 1) >> 1) * (H_DIM / 128) + hb);
        }

        const uint32_t sA = sbase + (it & 1) * G2_STAGE;
        const uint32_t sB = sA + G2_A_BYTES;
#pragma unroll
        for (int kk = 0; kk < 64; kk += 16) {
            uint32_t a2[2][4];
#pragma unroll
            for (int mi = 0; mi < 2; mi++)
                ldsm_x4(a2[mi], sA + (wm * 32 + mi * 16 + (l & 15)) * G2_PITCH +
                                   (kk + ((l >> 4) << 3)) * 2);
            uint32_t bf[4][2];
#pragma unroll
            for (int p = 0; p < 2; p++) {
                // ldmatrix.trans of [k][h] tile: (t&1)=k-half, (t>>1)=n-half
                int t = l >> 3, rr = l & 7;
                uint32_t baddr = sB + (kk + (t & 1) * 8 + rr) * G2_PITCH +
                                 (wn * 32 + p * 16 + (t >> 1) * 8) * 2;
                uint32_t r4[4];
                ldsm_x4_t(r4, baddr);
                bf[p * 2][0] = r4[0]; bf[p * 2][1] = r4[1];
                bf[p * 2 + 1][0] = r4[2]; bf[p * 2 + 1][1] = r4[3];
            }
#pragma unroll
            for (int mi = 0; mi < 2; mi++)
#pragma unroll
                for (int n = 0; n < 4; n++)
                    mma16816(c[mi][n], a2[mi], bf[n]);
        }

        if (it + 1 < NK2) {
            sts_b_g2(sm2 + ((it + 1) & 1) * G2_STAGE, tid, sv, b4);
            CP_WAIT0();
        }
        __syncthreads();
    }

    // Epilogue: fp32 stores
#pragma unroll
    for (int mi = 0; mi < 2; mi++)
#pragma unroll
        for (int n = 0; n < 4; n++) {
            int row = t0 + wm * 32 + mi * 16 + (l >> 2);
            int col = h0 + wn * 32 + n * 8 + ((l & 3) << 1);
            float2 v0 = make_float2(c[mi][n][0], c[mi][n][1]);
            float2 v1 = make_float2(c[mi][n][2], c[mi][n][3]);
            *(float2*)(out + (size_t)row * H_DIM + col) = v0;
            *(float2*)(out + (size_t)(row + 8) * H_DIM + col) = v1;
        }
}

// ---------------------------------------------------------------------------
// Launch
// ---------------------------------------------------------------------------
extern "C" void kernel_launch(void* const* d_in, const int* in_sizes, int n_in,
                              void* d_out, int out_size) {
    const float* x  = (const float*)d_in[0];
    const float* wg = (const float*)d_in[1];
    const float* wu = (const float*)d_in[2];
    const float* wd = (const float*)d_in[3];
    const float* sg = (const float*)d_in[4];
    const float* su = (const float*)d_in[5];
    const float* sd = (const float*)d_in[6];
    float* out = (float*)d_out;
    (void)in_sizes; (void)n_in; (void)out_size;

    cudaFuncSetAttribute(gemm1_kernel, cudaFuncAttributeMaxDynamicSharedMemorySize,
                         G1_SMEM);
    cudaFuncSetAttribute(gemm2_kernel, cudaFuncAttributeMaxDynamicSharedMemorySize,
                         G2_SMEM);

    cvt_x_kernel<<<(T_DIM * H_DIM / 4) / 256, 256>>>(x);
    // T-tiles fastest (blockIdx.x) so concurrent CTAs dedup weight reads in L2
    gemm1_kernel<<<dim3(T_DIM / 128, I_DIM / 64), 256, G1_SMEM>>>(wg, wu, sg, su);
    gemm2_kernel<<<dim3(T_DIM / 128, H_DIM / 64), 256, G2_SMEM>>>(wd, sd, out);
}